// round 1
// baseline (speedup 1.0000x reference)
#include <cuda_runtime.h>
#include <math.h>
#include <stdint.h>

#define NLVL 16
#define MAX_ENTRY (1u << 19)
#define HASH_MASK (MAX_ENTRY - 1u)

// Per-level parameters, computed on device to bit-match numpy's double math.
struct LvlP {
    float scale;   // res - 1.0
    float cap;     // (float)(res - 1.0001)
    int   res;
    int   res2;
    int   dense;   // 1 if res^3 < 2^19 (dense linear index), else hashed
};

__device__ LvlP g_lvl[NLVL];

__global__ void init_lvl_kernel() {
    int l = threadIdx.x;
    if (l < NLVL) {
        // mirrors: b = exp((log(2048)-log(16))/15); res = floor(16 * b**l)
        double step = (log(2048.0) - log(16.0)) / 15.0;
        double b = exp(step);
        double r = floor(16.0 * pow(b, (double)l));
        LvlP p;
        int res = (int)r;
        p.scale = (float)(r - 1.0);
        p.cap   = (float)(r - 1.0001);
        p.res   = res;
        p.res2  = res * res;
        p.dense = ((r * r * r) < (double)MAX_ENTRY) ? 1 : 0;
        g_lvl[l] = p;
    }
}

__global__ __launch_bounds__(256)
void grid_lookup_kernel(const float* __restrict__ x,
                        const float* __restrict__ tables,
                        float* __restrict__ out,
                        int n)
{
    int i = blockIdx.x * 256 + threadIdx.x;
    if (i >= n) return;

    float px = __ldg(&x[3 * i + 0]);
    float py = __ldg(&x[3 * i + 1]);
    float pz = __ldg(&x[3 * i + 2]);

    const float2* __restrict__ tbl = (const float2*)tables;

    float res_out[2 * NLVL];

#pragma unroll 1
    for (int l = 0; l < NLVL; ++l) {
        LvlP p = g_lvl[l];

        // to_hash_space: clip(x*(res-1), 0, res-1.0001), all in f32 like the ref
        float cx = fminf(fmaxf(px * p.scale, 0.0f), p.cap);
        float cy = fminf(fmaxf(py * p.scale, 0.0f), p.cap);
        float cz = fminf(fmaxf(pz * p.scale, 0.0f), p.cap);
        float fx = floorf(cx), fy = floorf(cy), fz = floorf(cz);
        int ix = (int)fx, iy = (int)fy, iz = (int)fz;

        float xw = cx - fx, yw = cy - fy, zw = cz - fz;
        float wxa[2] = {1.0f - xw, xw};
        float wya[2] = {1.0f - yw, yw};
        float wza[2] = {1.0f - zw, zw};

        unsigned int idx[8];
        if (p.dense) {
            // exact: integer linear index (< 2^19, matches ref's f32 computation)
            unsigned int base = (unsigned int)(ix + iy * p.res + iz * p.res2);
            unsigned int dr = (unsigned int)p.res;
            unsigned int dr2 = (unsigned int)p.res2;
            // corner c: bits (x=c>>2, y=(c>>1)&1, z=c&1), OFFSETS order
            idx[0] = base;
            idx[1] = base + dr2;
            idx[2] = base + dr;
            idx[3] = base + dr + dr2;
            idx[4] = base + 1u;
            idx[5] = base + 1u + dr2;
            idx[6] = base + 1u + dr;
            idx[7] = base + 1u + dr + dr2;
        } else {
            // xor-prime hash mod 2^19: only low 19 bits survive -> uint32 math is exact
            unsigned int h0a = (unsigned int)ix * 3367900313u;
            unsigned int h0b = (unsigned int)(ix + 1) * 3367900313u;
            unsigned int h1a = (unsigned int)iy * 2654435761u;
            unsigned int h1b = (unsigned int)(iy + 1) * 2654435761u;
            unsigned int h2a = (unsigned int)iz * 805459861u;
            unsigned int h2b = (unsigned int)(iz + 1) * 805459861u;
            idx[0] = (h0a ^ h1a ^ h2a) & HASH_MASK;
            idx[1] = (h0a ^ h1a ^ h2b) & HASH_MASK;
            idx[2] = (h0a ^ h1b ^ h2a) & HASH_MASK;
            idx[3] = (h0a ^ h1b ^ h2b) & HASH_MASK;
            idx[4] = (h0b ^ h1a ^ h2a) & HASH_MASK;
            idx[5] = (h0b ^ h1a ^ h2b) & HASH_MASK;
            idx[6] = (h0b ^ h1b ^ h2a) & HASH_MASK;
            idx[7] = (h0b ^ h1b ^ h2b) & HASH_MASK;
        }

        const float2* __restrict__ t = tbl + (size_t)l * MAX_ENTRY;

        float accx = 0.0f, accy = 0.0f;
#pragma unroll
        for (int c = 0; c < 8; ++c) {
            float w = wxa[(c >> 2) & 1] * wya[(c >> 1) & 1] * wza[c & 1];
            float2 v = __ldg(&t[idx[c]]);
            accx = fmaf(w, v.x, accx);
            accy = fmaf(w, v.y, accy);
        }
        res_out[2 * l + 0] = accx;
        res_out[2 * l + 1] = accy;
    }

    // coalesced 128B-per-thread output: 8 x float4
    float4* o = (float4*)(out + (size_t)i * (2 * NLVL));
#pragma unroll
    for (int k = 0; k < 8; ++k) {
        o[k] = ((const float4*)res_out)[k];
    }
}

extern "C" void kernel_launch(void* const* d_in, const int* in_sizes, int n_in,
                              void* d_out, int out_size) {
    const float* x      = (const float*)d_in[0];   // (N, 3) f32
    const float* tables = (const float*)d_in[1];   // (16, 2^19, 2) f32
    float* out = (float*)d_out;                    // (N, 32) f32

    int n = in_sizes[0] / 3;

    init_lvl_kernel<<<1, 32>>>();
    int blocks = (n + 255) / 256;
    grid_lookup_kernel<<<blocks, 256>>>(x, tables, out, n);
}